// round 12
// baseline (speedup 1.0000x reference)
#include <cuda_runtime.h>
#include <cuda_fp16.h>
#include <cstdint>
#include <cstddef>

#define SLEN   4096
#define BATCH  2
#define DMODEL 768
#define NHEADS 12
#define HDIM   64
#define MROWS  (BATCH * SLEN)   // 8192
#define NQKV   (3 * DMODEL)     // 2304

// ---------------- scratch (__device__ globals) -----------------------------
__device__ __half g_xh[(size_t)MROWS * DMODEL];
__device__ __half g_wqkvh[(size_t)DMODEL * NQKV];   // [N][K]
__device__ __half g_wouth[(size_t)DMODEL * DMODEL]; // [N][K]
__device__ __half g_qkvh[(size_t)MROWS * NQKV];     // fp16 Q|K|V
__device__ __half g_ctxh[(size_t)MROWS * DMODEL];

// ---------------- helpers --------------------------------------------------
__device__ __forceinline__ uint32_t s2u(const void* p) {
    return (uint32_t)__cvta_generic_to_shared(p);
}
__device__ __forceinline__ uint32_t swz(uint32_t b) {           // SW128
    return b ^ ((b >> 3) & 0x70);
}
__device__ __forceinline__ void ldsm4(uint32_t r[4], uint32_t addr) {
    asm volatile("ldmatrix.sync.aligned.m8n8.x4.shared.b16 {%0,%1,%2,%3}, [%4];"
                 : "=r"(r[0]), "=r"(r[1]), "=r"(r[2]), "=r"(r[3]) : "r"(addr));
}
__device__ __forceinline__ void ldsm4t(uint32_t r[4], uint32_t addr) {
    asm volatile("ldmatrix.sync.aligned.m8n8.x4.trans.shared.b16 {%0,%1,%2,%3}, [%4];"
                 : "=r"(r[0]), "=r"(r[1]), "=r"(r[2]), "=r"(r[3]) : "r"(addr));
}
__device__ __forceinline__ void cp16(uint32_t dst, const void* src) {
    asm volatile("cp.async.cg.shared.global [%0], [%1], 16;" :: "r"(dst), "l"(src));
}
__device__ __forceinline__ void mma_f16(float c[4], const uint32_t a[4],
                                        const uint32_t b[2]) {
    asm volatile(
        "mma.sync.aligned.m16n8k16.row.col.f32.f16.f16.f32 "
        "{%0,%1,%2,%3}, {%4,%5,%6,%7}, {%8,%9}, {%0,%1,%2,%3};\n"
        : "+f"(c[0]), "+f"(c[1]), "+f"(c[2]), "+f"(c[3])
        : "r"(a[0]), "r"(a[1]), "r"(a[2]), "r"(a[3]), "r"(b[0]), "r"(b[1]));
}
__device__ __forceinline__ unsigned pack2(float x, float y) {
    __half2 h = __floats2half2_rn(x, y);
    return *reinterpret_cast<unsigned*>(&h);
}
// 2^x on a packed half2 pair (inputs given as two floats)
__device__ __forceinline__ uint32_t ex2h2(float x, float y) {
    uint32_t h = pack2(x, y);
    uint32_t r;
    asm("ex2.approx.f16x2 %0, %1;" : "=r"(r) : "r"(h));
    return r;
}

// ---------------- converts -------------------------------------------------
__global__ void to_half(const float* __restrict__ src, __half* __restrict__ dst, int n4) {
    int i = blockIdx.x * blockDim.x + threadIdx.x;
    int stride = gridDim.x * blockDim.x;
    for (; i < n4; i += stride) {
        float4 v = reinterpret_cast<const float4*>(src)[i];
        reinterpret_cast<__half2*>(dst)[2 * i]     = __floats2half2_rn(v.x, v.y);
        reinterpret_cast<__half2*>(dst)[2 * i + 1] = __floats2half2_rn(v.z, v.w);
    }
}

// W[K][N] fp32 -> WT[N][K] fp16 (transpose + convert)
__global__ void conv_wT(const float* __restrict__ W, __half* __restrict__ WT,
                        int K, int N) {
    __shared__ float t[32][33];
    const int k0 = blockIdx.y * 32, n0 = blockIdx.x * 32;
    const int tx = threadIdx.x & 31, ty = threadIdx.x >> 5;
#pragma unroll
    for (int m = 0; m < 4; m++)
        t[ty + 8 * m][tx] = W[(size_t)(k0 + ty + 8 * m) * N + n0 + tx];
    __syncthreads();
#pragma unroll
    for (int m = 0; m < 4; m++)
        WT[(size_t)(n0 + ty + 8 * m) * K + k0 + tx] = __float2half_rn(t[tx][ty + 8 * m]);
}

// ---------------- 1-pass fp16 GEMM: C = A @ B^T (2-stage, proven) ----------
#define GBUF 32768   // bytes per buffer (A 16K + B 16K)
template <bool WRITE_HALF>
__global__ __launch_bounds__(256, 2)
void hgemm(const __half* __restrict__ A, const __half* __restrict__ Bt,
           float* __restrict__ Cf, __half* __restrict__ Ch,
           int M, int N, int K) {
    extern __shared__ __half sm[];
    const int tid = threadIdx.x, lane = tid & 31, w = tid >> 5;
    const int gid = lane >> 2, tig = lane & 3;
    const int wm = (w >> 2) * 64, wn = (w & 3) * 32;
    const int bm = blockIdx.y * 128, bn = blockIdx.x * 128;
    const uint32_t sb = s2u(sm);

    float acc[4][4][4];
#pragma unroll
    for (int i = 0; i < 4; i++)
#pragma unroll
        for (int j = 0; j < 4; j++)
#pragma unroll
            for (int e = 0; e < 4; e++) acc[i][j][e] = 0.f;

    const int nit = K >> 6;

#define G_LOAD(k0, buf)                                                         \
    {                                                                           \
        uint32_t bb = sb + (uint32_t)(buf) * GBUF;                              \
        _Pragma("unroll")                                                       \
        for (int p = 0; p < 4; p++) {                                           \
            int id = tid + p * 256;                                             \
            int row = id >> 3, chB = (id & 7) << 4;                             \
            uint32_t so = swz((uint32_t)(row * 128 + chB));                     \
            cp16(bb + so,                                                       \
                 (const char*)(A + (size_t)(bm + row) * K + (k0)) + chB);       \
            cp16(bb + 16384 + so,                                               \
                 (const char*)(Bt + (size_t)(bn + row) * K + (k0)) + chB);      \
        }                                                                       \
        asm volatile("cp.async.commit_group;" ::: "memory");                    \
    }

    G_LOAD(0, 0);

    const int arow  = lane & 15;
    const int acolB = ((lane >> 4) << 3) * 2;
    const int brow  = ((lane >> 4) << 3) + (lane & 7);
    const int bcolB = (((lane >> 3) & 1) << 3) * 2;

    for (int it = 0; it < nit; it++) {
        asm volatile("cp.async.wait_group 0;" ::: "memory");
        __syncthreads();
        if (it + 1 < nit) G_LOAD((it + 1) << 6, (it + 1) & 1);

        uint32_t aB = sb + (uint32_t)(it & 1) * GBUF;
        uint32_t bB = aB + 16384;
#pragma unroll
        for (int kk = 0; kk < 64; kk += 16) {
            uint32_t af[4][4];
#pragma unroll
            for (int i = 0; i < 4; i++)
                ldsm4(af[i], aB + swz((uint32_t)((wm + 16 * i + arow) * 128 +
                                                 kk * 2 + acolB)));
#pragma unroll
            for (int jp = 0; jp < 2; jp++) {
                uint32_t bh[4];
                ldsm4(bh, bB + swz((uint32_t)((wn + 16 * jp + brow) * 128 +
                                              kk * 2 + bcolB)));
#pragma unroll
                for (int i = 0; i < 4; i++) {
                    mma_f16(acc[i][2 * jp],     af[i], &bh[0]);
                    mma_f16(acc[i][2 * jp + 1], af[i], &bh[2]);
                }
            }
        }
        __syncthreads();
    }

    // epilogue
#pragma unroll
    for (int i = 0; i < 4; i++)
#pragma unroll
        for (int j = 0; j < 4; j++) {
            int r0 = bm + wm + i * 16 + gid;
            int cc = bn + wn + j * 8 + 2 * tig;
            if (WRITE_HALF) {
                *(__half2*)(Ch + (size_t)r0 * N + cc) =
                    __floats2half2_rn(acc[i][j][0], acc[i][j][1]);
                *(__half2*)(Ch + (size_t)(r0 + 8) * N + cc) =
                    __floats2half2_rn(acc[i][j][2], acc[i][j][3]);
            } else {
                *(float2*)(Cf + (size_t)r0 * N + cc) =
                    make_float2(acc[i][j][0], acc[i][j][1]);
                *(float2*)(Cf + (size_t)(r0 + 8) * N + cc) =
                    make_float2(acc[i][j][2], acc[i][j][3]);
            }
        }
}

// ---------------- fp16 flash attention, BQ=128, 128-key steps --------------
// p = 2^s directly; l via ones-column MMA. 4 KV buffers (two pairs);
// ONE wait+sync per 128 keys, 72-MMA unbarriered span per tile pair.
// dyn smem halves: Q[128][72] @0; K[4][64][72] @9216; V[4][64][72] @27648
#define QSTR 72
#define ATT_KOFF 9216
#define ATT_VOFF 27648
#define ATT_BUFH 4608
#define ATT_SMEM 92160
__global__ __launch_bounds__(256, 2)
void attn_mma() {
    extern __shared__ __half asm_[];
    const uint32_t sb = s2u(asm_);
    const int tid  = threadIdx.x;
    const int lane = tid & 31;
    const int w    = tid >> 5;
    const int gid  = lane >> 2;
    const int tig  = lane & 3;
    // Reverse order: heaviest q-tiles launch first.
    const int qt = gridDim.x - 1 - blockIdx.x;
    const int h = blockIdx.y, b = blockIdx.z;
    const int qbase = qt * 128;
    const size_t rowb = (size_t)b * SLEN;
    // Q pre-scale: (1/8) * log2(e) -> logits in log2 domain.
    const __half2 qscale = __floats2half2_rn(0.18033688f, 0.18033688f);

    // Load Q tile (128x64)
#pragma unroll
    for (int t = 0; t < 8; t++) {
        int c = tid + t * 256;
        int r = c >> 4, dc = (c & 15) << 2;
        uint2 v = *(const uint2*)(g_qkvh + (rowb + qbase + r) * NQKV + h * HDIM + dc);
        *(__half2*)&asm_[r * QSTR + dc]     = __hmul2(*reinterpret_cast<__half2*>(&v.x), qscale);
        *(__half2*)&asm_[r * QSTR + dc + 2] = __hmul2(*reinterpret_cast<__half2*>(&v.y), qscale);
    }

// load one 64-key K+V tile into buffer slot buf_ (0..3); one commit
#define KV_LOAD(kb_, buf_)                                                         \
    {                                                                              \
        _Pragma("unroll")                                                          \
        for (int p = 0; p < 2; p++) {                                              \
            int id = tid + p * 256;                                                \
            int r = id >> 3, chB = (id & 7) << 4;                                  \
            uint32_t off = (uint32_t)(buf_) * (ATT_BUFH * 2) +                     \
                           (uint32_t)(r * (QSTR * 2) + chB);                       \
            cp16(sb + ATT_KOFF * 2 + off,                                          \
                 (const char*)(g_qkvh + (rowb + (kb_) + r) * NQKV + DMODEL +       \
                               h * HDIM) + chB);                                   \
            cp16(sb + ATT_VOFF * 2 + off,                                          \
                 (const char*)(g_qkvh + (rowb + (kb_) + r) * NQKV + 2 * DMODEL +   \
                               h * HDIM) + chB);                                   \
        }                                                                          \
        asm volatile("cp.async.commit_group;" ::: "memory");                       \
    }

// one 64-key tile of attention: S-MMA, (optional mask), ex2, l-MMA, PV-MMA
#define ATT_TILE(kb_, kB_, vB_, MASKED)                                            \
    if (!(MASKED) || (kb_) <= wrow_hi) {                                           \
        float s[8][4];                                                             \
        _Pragma("unroll")                                                          \
        for (int j = 0; j < 8; j++)                                                \
            _Pragma("unroll")                                                      \
            for (int e = 0; e < 4; e++) s[j][e] = 0.f;                             \
        _Pragma("unroll")                                                          \
        for (int kk4 = 0; kk4 < 4; kk4++) {                                        \
            _Pragma("unroll")                                                      \
            for (int jp = 0; jp < 4; jp++) {                                       \
                uint32_t bk[4];                                                    \
                ldsm4(bk, (kB_) + (uint32_t)((jp * 16 + brow) * (QSTR * 2) +       \
                                             kk4 * 32 + bcolB));                   \
                mma_f16(s[2 * jp],     aq[kk4], &bk[0]);                           \
                mma_f16(s[2 * jp + 1], aq[kk4], &bk[2]);                           \
            }                                                                      \
        }                                                                          \
        if (MASKED) {                                                              \
            _Pragma("unroll")                                                      \
            for (int j = 0; j < 8; j++) {                                          \
                int c0 = (kb_) + 8 * j + 2 * tig;                                  \
                if (c0 > row0)     s[j][0] = -30000.f;                             \
                if (c0 + 1 > row0) s[j][1] = -30000.f;                             \
                if (c0 > row1)     s[j][2] = -30000.f;                             \
                if (c0 + 1 > row1) s[j][3] = -30000.f;                             \
            }                                                                      \
        }                                                                          \
        uint32_t pa[4][4];                                                         \
        _Pragma("unroll")                                                          \
        for (int kc = 0; kc < 4; kc++) {                                           \
            pa[kc][0] = ex2h2(s[2 * kc][0],     s[2 * kc][1]);                     \
            pa[kc][1] = ex2h2(s[2 * kc][2],     s[2 * kc][3]);                     \
            pa[kc][2] = ex2h2(s[2 * kc + 1][0], s[2 * kc + 1][1]);                 \
            pa[kc][3] = ex2h2(s[2 * kc + 1][2], s[2 * kc + 1][3]);                 \
        }                                                                          \
        _Pragma("unroll")                                                          \
        for (int kc = 0; kc < 4; kc++)                                             \
            mma_f16(lacc, pa[kc], onesb);                                          \
        _Pragma("unroll")                                                          \
        for (int kc = 0; kc < 4; kc++)                                             \
            _Pragma("unroll")                                                      \
            for (int jp = 0; jp < 4; jp++) {                                       \
                uint32_t bv[4];                                                    \
                ldsm4t(bv, (vB_) + (uint32_t)((kc * 16 + vrow) * (QSTR * 2) +      \
                                              jp * 32 + vcolB));                   \
                mma_f16(o[2 * jp],     pa[kc], &bv[0]);                            \
                mma_f16(o[2 * jp + 1], pa[kc], &bv[2]);                            \
            }                                                                      \
    }

    float o[8][4];
#pragma unroll
    for (int j = 0; j < 8; j++)
#pragma unroll
        for (int e = 0; e < 4; e++) o[j][e] = 0.f;
    float lacc[4] = {0.f, 0.f, 0.f, 0.f};  // row sums via ones-MMA
    const uint32_t onesb[2] = {0x3C003C00u, 0x3C003C00u};

    const int arow  = lane & 15;
    const int acolB = ((lane >> 4) << 3) * 2;
    const int brow  = ((lane >> 4) << 3) + (lane & 7);
    const int bcolB = (((lane >> 3) & 1) << 3) * 2;
    const int vrow  = (lane & 7) + (((lane >> 3) & 1) << 3);
    const int vcolB = (lane >> 4) << 4;
    const int wrow_lo = qbase + w * 16;
    const int wrow_hi = wrow_lo + 15;
    const int row0 = wrow_lo + gid;
    const int row1 = row0 + 8;
    const uint32_t qB = sb;

    const int nsteps = qt + 1;        // 128-key steps (nkt=2qt+2 is even)
    KV_LOAD(0, 0);
    KV_LOAD(64, 1);

    // Hoist Q fragments into registers
    __syncthreads();
    uint32_t aq[4][4];
#pragma unroll
    for (int kk4 = 0; kk4 < 4; kk4++)
        ldsm4(aq[kk4], qB + (uint32_t)((w * 16 + arow) * (QSTR * 2) +
                                       kk4 * 32 + acolB));

    for (int st = 0; st < nsteps; st++) {
        const int kb0 = st * 128;
        asm volatile("cp.async.wait_group 0;" ::: "memory");
        __syncthreads();
        if (st + 1 < nsteps) {
            const int nb = ((st + 1) & 1) * 2;
            KV_LOAD(kb0 + 128, nb);
            KV_LOAD(kb0 + 192, nb + 1);
        }
        const int cb = (st & 1) * 2;
        const uint32_t kB0 = sb + ATT_KOFF * 2 + (uint32_t)cb * (ATT_BUFH * 2);
        const uint32_t vB0 = sb + ATT_VOFF * 2 + (uint32_t)cb * (ATT_BUFH * 2);

        if (st < nsteps - 1) {
            ATT_TILE(kb0,      kB0,                  vB0,                  0);
            ATT_TILE(kb0 + 64, kB0 + ATT_BUFH * 2,   vB0 + ATT_BUFH * 2,   0);
        } else {
            ATT_TILE(kb0,      kB0,                  vB0,                  1);
            ATT_TILE(kb0 + 64, kB0 + ATT_BUFH * 2,   vB0 + ATT_BUFH * 2,   1);
        }
    }

    // normalize, store fp16 ctx  (lacc[0] = row0 sum, lacc[2] = row1 sum)
    const float inv0 = 1.f / lacc[0], inv1 = 1.f / lacc[2];
    const size_t r0g = rowb + qbase + w * 16 + gid;
#pragma unroll
    for (int j = 0; j < 8; j++) {
        int col = h * HDIM + 8 * j + 2 * tig;
        *(__half2*)(g_ctxh + r0g * DMODEL + col) =
            __floats2half2_rn(o[j][0] * inv0, o[j][1] * inv0);
        *(__half2*)(g_ctxh + (r0g + 8) * DMODEL + col) =
            __floats2half2_rn(o[j][2] * inv1, o[j][3] * inv1);
    }
}

// ---------------------------------------------------------------------------
extern "C" void kernel_launch(void* const* d_in, const int* in_sizes, int n_in,
                              void* d_out, int out_size) {
    const float* x     = (const float*)d_in[0];
    const float* w_qkv = (const float*)d_in[1];
    const float* w_out = (const float*)d_in[2];
    float* out = (float*)d_out;

    __half *xh, *wqh, *woh, *qkvh, *ctxh;
    cudaGetSymbolAddress((void**)&xh,   g_xh);
    cudaGetSymbolAddress((void**)&wqh,  g_wqkvh);
    cudaGetSymbolAddress((void**)&woh,  g_wouth);
    cudaGetSymbolAddress((void**)&qkvh, g_qkvh);
    cudaGetSymbolAddress((void**)&ctxh, g_ctxh);

    const int smemGemm = 2 * GBUF;  // 65536 B
    cudaFuncSetAttribute(hgemm<true>,
                         cudaFuncAttributeMaxDynamicSharedMemorySize, smemGemm);
    cudaFuncSetAttribute(hgemm<false>,
                         cudaFuncAttributeMaxDynamicSharedMemorySize, smemGemm);
    cudaFuncSetAttribute(attn_mma,
                         cudaFuncAttributeMaxDynamicSharedMemorySize, ATT_SMEM);

    to_half<<<256, 256>>>(x, xh, MROWS * DMODEL / 4);
    conv_wT<<<dim3(NQKV / 32, DMODEL / 32), 256>>>(w_qkv, wqh, DMODEL, NQKV);
    conv_wT<<<dim3(DMODEL / 32, DMODEL / 32), 256>>>(w_out, woh, DMODEL, DMODEL);

    // QKV projection (fp16 out): [8192,768] @ [768,2304]
    hgemm<true><<<dim3(NQKV / 128, MROWS / 128), 256, smemGemm>>>(
        xh, wqh, nullptr, qkvh, MROWS, NQKV, DMODEL);

    // causal attention -> ctx
    attn_mma<<<dim3(SLEN / 128, NHEADS, BATCH), 256, ATT_SMEM>>>();

    // output projection (fp32 out): [8192,768] @ [768,768]
    hgemm<false><<<dim3(DMODEL / 128, MROWS / 128), 256, smemGemm>>>(
        ctxh, woh, out, nullptr, MROWS, DMODEL, DMODEL);
}

// round 13
// speedup vs baseline: 1.0058x; 1.0058x over previous
#include <cuda_runtime.h>
#include <cuda_fp16.h>
#include <cstdint>
#include <cstddef>

#define SLEN   4096
#define BATCH  2
#define DMODEL 768
#define NHEADS 12
#define HDIM   64
#define MROWS  (BATCH * SLEN)   // 8192
#define NQKV   (3 * DMODEL)     // 2304

// ---------------- scratch (__device__ globals) -----------------------------
__device__ __half g_xh[(size_t)MROWS * DMODEL];
__device__ __half g_wqkvh[(size_t)DMODEL * NQKV];   // [N][K]
__device__ __half g_wouth[(size_t)DMODEL * DMODEL]; // [N][K]
__device__ __half g_qkvh[(size_t)MROWS * NQKV];     // fp16 Q|K|V
__device__ __half g_ctxh[(size_t)MROWS * DMODEL];

// ---------------- helpers --------------------------------------------------
__device__ __forceinline__ uint32_t s2u(const void* p) {
    return (uint32_t)__cvta_generic_to_shared(p);
}
__device__ __forceinline__ uint32_t swz(uint32_t b) {           // SW128
    return b ^ ((b >> 3) & 0x70);
}
__device__ __forceinline__ void ldsm4(uint32_t r[4], uint32_t addr) {
    asm volatile("ldmatrix.sync.aligned.m8n8.x4.shared.b16 {%0,%1,%2,%3}, [%4];"
                 : "=r"(r[0]), "=r"(r[1]), "=r"(r[2]), "=r"(r[3]) : "r"(addr));
}
__device__ __forceinline__ void ldsm4t(uint32_t r[4], uint32_t addr) {
    asm volatile("ldmatrix.sync.aligned.m8n8.x4.trans.shared.b16 {%0,%1,%2,%3}, [%4];"
                 : "=r"(r[0]), "=r"(r[1]), "=r"(r[2]), "=r"(r[3]) : "r"(addr));
}
__device__ __forceinline__ void cp16(uint32_t dst, const void* src) {
    asm volatile("cp.async.cg.shared.global [%0], [%1], 16;" :: "r"(dst), "l"(src));
}
__device__ __forceinline__ void mma_f16(float c[4], const uint32_t a[4],
                                        const uint32_t b[2]) {
    asm volatile(
        "mma.sync.aligned.m16n8k16.row.col.f32.f16.f16.f32 "
        "{%0,%1,%2,%3}, {%4,%5,%6,%7}, {%8,%9}, {%0,%1,%2,%3};\n"
        : "+f"(c[0]), "+f"(c[1]), "+f"(c[2]), "+f"(c[3])
        : "r"(a[0]), "r"(a[1]), "r"(a[2]), "r"(a[3]), "r"(b[0]), "r"(b[1]));
}
__device__ __forceinline__ unsigned pack2(float x, float y) {
    __half2 h = __floats2half2_rn(x, y);
    return *reinterpret_cast<unsigned*>(&h);
}
// 2^x on a packed half2 pair (inputs given as two floats)
__device__ __forceinline__ uint32_t ex2h2(float x, float y) {
    uint32_t h = pack2(x, y);
    uint32_t r;
    asm("ex2.approx.f16x2 %0, %1;" : "=r"(r) : "r"(h));
    return r;
}

// ---------------- converts -------------------------------------------------
__global__ void to_half(const float* __restrict__ src, __half* __restrict__ dst, int n4) {
    int i = blockIdx.x * blockDim.x + threadIdx.x;
    int stride = gridDim.x * blockDim.x;
    for (; i < n4; i += stride) {
        float4 v = reinterpret_cast<const float4*>(src)[i];
        reinterpret_cast<__half2*>(dst)[2 * i]     = __floats2half2_rn(v.x, v.y);
        reinterpret_cast<__half2*>(dst)[2 * i + 1] = __floats2half2_rn(v.z, v.w);
    }
}

// W[K][N] fp32 -> WT[N][K] fp16 (transpose + convert)
__global__ void conv_wT(const float* __restrict__ W, __half* __restrict__ WT,
                        int K, int N) {
    __shared__ float t[32][33];
    const int k0 = blockIdx.y * 32, n0 = blockIdx.x * 32;
    const int tx = threadIdx.x & 31, ty = threadIdx.x >> 5;
#pragma unroll
    for (int m = 0; m < 4; m++)
        t[ty + 8 * m][tx] = W[(size_t)(k0 + ty + 8 * m) * N + n0 + tx];
    __syncthreads();
#pragma unroll
    for (int m = 0; m < 4; m++)
        WT[(size_t)(n0 + ty + 8 * m) * K + k0 + tx] = __float2half_rn(t[tx][ty + 8 * m]);
}

// ---------------- 1-pass fp16 GEMM: C = A @ B^T (2-stage, proven) ----------
#define GBUF 32768   // bytes per buffer (A 16K + B 16K)
template <bool WRITE_HALF>
__global__ __launch_bounds__(256, 2)
void hgemm(const __half* __restrict__ A, const __half* __restrict__ Bt,
           float* __restrict__ Cf, __half* __restrict__ Ch,
           int M, int N, int K) {
    extern __shared__ __half sm[];
    const int tid = threadIdx.x, lane = tid & 31, w = tid >> 5;
    const int gid = lane >> 2, tig = lane & 3;
    const int wm = (w >> 2) * 64, wn = (w & 3) * 32;
    const int bm = blockIdx.y * 128, bn = blockIdx.x * 128;
    const uint32_t sb = s2u(sm);

    float acc[4][4][4];
#pragma unroll
    for (int i = 0; i < 4; i++)
#pragma unroll
        for (int j = 0; j < 4; j++)
#pragma unroll
            for (int e = 0; e < 4; e++) acc[i][j][e] = 0.f;

    const int nit = K >> 6;

#define G_LOAD(k0, buf)                                                         \
    {                                                                           \
        uint32_t bb = sb + (uint32_t)(buf) * GBUF;                              \
        _Pragma("unroll")                                                       \
        for (int p = 0; p < 4; p++) {                                           \
            int id = tid + p * 256;                                             \
            int row = id >> 3, chB = (id & 7) << 4;                             \
            uint32_t so = swz((uint32_t)(row * 128 + chB));                     \
            cp16(bb + so,                                                       \
                 (const char*)(A + (size_t)(bm + row) * K + (k0)) + chB);       \
            cp16(bb + 16384 + so,                                               \
                 (const char*)(Bt + (size_t)(bn + row) * K + (k0)) + chB);      \
        }                                                                       \
        asm volatile("cp.async.commit_group;" ::: "memory");                    \
    }

    G_LOAD(0, 0);

    const int arow  = lane & 15;
    const int acolB = ((lane >> 4) << 3) * 2;
    const int brow  = ((lane >> 4) << 3) + (lane & 7);
    const int bcolB = (((lane >> 3) & 1) << 3) * 2;

    for (int it = 0; it < nit; it++) {
        asm volatile("cp.async.wait_group 0;" ::: "memory");
        __syncthreads();
        if (it + 1 < nit) G_LOAD((it + 1) << 6, (it + 1) & 1);

        uint32_t aB = sb + (uint32_t)(it & 1) * GBUF;
        uint32_t bB = aB + 16384;
#pragma unroll
        for (int kk = 0; kk < 64; kk += 16) {
            uint32_t af[4][4];
#pragma unroll
            for (int i = 0; i < 4; i++)
                ldsm4(af[i], aB + swz((uint32_t)((wm + 16 * i + arow) * 128 +
                                                 kk * 2 + acolB)));
#pragma unroll
            for (int jp = 0; jp < 2; jp++) {
                uint32_t bh[4];
                ldsm4(bh, bB + swz((uint32_t)((wn + 16 * jp + brow) * 128 +
                                              kk * 2 + bcolB)));
#pragma unroll
                for (int i = 0; i < 4; i++) {
                    mma_f16(acc[i][2 * jp],     af[i], &bh[0]);
                    mma_f16(acc[i][2 * jp + 1], af[i], &bh[2]);
                }
            }
        }
        __syncthreads();
    }

    // epilogue
#pragma unroll
    for (int i = 0; i < 4; i++)
#pragma unroll
        for (int j = 0; j < 4; j++) {
            int r0 = bm + wm + i * 16 + gid;
            int cc = bn + wn + j * 8 + 2 * tig;
            if (WRITE_HALF) {
                *(__half2*)(Ch + (size_t)r0 * N + cc) =
                    __floats2half2_rn(acc[i][j][0], acc[i][j][1]);
                *(__half2*)(Ch + (size_t)(r0 + 8) * N + cc) =
                    __floats2half2_rn(acc[i][j][2], acc[i][j][3]);
            } else {
                *(float2*)(Cf + (size_t)r0 * N + cc) =
                    make_float2(acc[i][j][0], acc[i][j][1]);
                *(float2*)(Cf + (size_t)(r0 + 8) * N + cc) =
                    make_float2(acc[i][j][2], acc[i][j][3]);
            }
        }
}

// ---------------- fp16 flash attention, BQ=128, SW128-swizzled smem --------
// Identical math to R9 (static-max softmax, ones-MMA row sums). Smem layout
// now 128B rows + SW128 swizzle (same as hgemm) so cp.async fills are
// bank-conflict-free.
// dyn smem bytes: Q[128][128B] @0; K[2][64][128B] @16384; V[2][64][128B] @32768
#define ATT_BUFB 8192
#define ATT_KOFF 16384
#define ATT_VOFF 32768
#define ATT_SMEM 49152
__global__ __launch_bounds__(256, 2)
void attn_mma() {
    extern __shared__ __half asm_[];
    const uint32_t sb = s2u(asm_);
    const int tid  = threadIdx.x;
    const int lane = tid & 31;
    const int w    = tid >> 5;
    const int gid  = lane >> 2;
    const int tig  = lane & 3;
    // Reverse order: heaviest q-tiles launch first.
    const int qt = gridDim.x - 1 - blockIdx.x;
    const int h = blockIdx.y, b = blockIdx.z;
    const int qbase = qt * 128;
    const size_t rowb = (size_t)b * SLEN;
    // Q pre-scale: (1/8) * log2(e) -> logits in log2 domain.
    const __half2 qscale = __floats2half2_rn(0.18033688f, 0.18033688f);

    // Load Q tile (128 rows x 64 halves = 128B rows), swizzled 8B stores
#pragma unroll
    for (int t = 0; t < 8; t++) {
        int c = tid + t * 256;
        int r = c >> 4, dc = (c & 15) << 2;           // dc in halves (mult of 4)
        uint2 v = *(const uint2*)(g_qkvh + (rowb + qbase + r) * NQKV + h * HDIM + dc);
        __half2 v0 = __hmul2(*reinterpret_cast<__half2*>(&v.x), qscale);
        __half2 v1 = __hmul2(*reinterpret_cast<__half2*>(&v.y), qscale);
        uint2 pkd = make_uint2(*(uint32_t*)&v0, *(uint32_t*)&v1);
        *(uint2*)((char*)asm_ + swz((uint32_t)(r * 128 + dc * 2))) = pkd;
    }

#define KV_LOAD(kb_, buf_)                                                         \
    {                                                                              \
        _Pragma("unroll")                                                          \
        for (int p = 0; p < 2; p++) {                                              \
            int id = tid + p * 256;                                                \
            int r = id >> 3, chB = (id & 7) << 4;                                  \
            uint32_t so = (uint32_t)(buf_) * ATT_BUFB +                            \
                          swz((uint32_t)(r * 128 + chB));                          \
            cp16(sb + ATT_KOFF + so,                                               \
                 (const char*)(g_qkvh + (rowb + (kb_) + r) * NQKV + DMODEL +       \
                               h * HDIM) + chB);                                   \
            cp16(sb + ATT_VOFF + so,                                               \
                 (const char*)(g_qkvh + (rowb + (kb_) + r) * NQKV + 2 * DMODEL +   \
                               h * HDIM) + chB);                                   \
        }                                                                          \
        asm volatile("cp.async.commit_group;" ::: "memory");                       \
    }

    float o[8][4];
#pragma unroll
    for (int j = 0; j < 8; j++)
#pragma unroll
        for (int e = 0; e < 4; e++) o[j][e] = 0.f;
    float lacc[4] = {0.f, 0.f, 0.f, 0.f};  // row sums via ones-MMA
    const uint32_t onesb[2] = {0x3C003C00u, 0x3C003C00u};

    const int arow  = lane & 15;
    const int acolB = ((lane >> 4) << 3) * 2;
    const int brow  = ((lane >> 4) << 3) + (lane & 7);
    const int bcolB = (((lane >> 3) & 1) << 3) * 2;
    const int vrow  = (lane & 7) + (((lane >> 3) & 1) << 3);
    const int vcolB = (lane >> 4) << 4;
    const int row0 = qbase + w * 16 + gid;
    const int row1 = row0 + 8;

    const int nkt = 2 * qt + 2;
    KV_LOAD(0, 0);

    // Hoist Q fragments into registers (Q smem stable across key loop)
    __syncthreads();
    uint32_t aq[4][4];
#pragma unroll
    for (int kk4 = 0; kk4 < 4; kk4++)
        ldsm4(aq[kk4], sb + swz((uint32_t)((w * 16 + arow) * 128 +
                                           kk4 * 32 + acolB)));

    for (int kt = 0; kt < nkt; kt++) {
        const int buf = kt & 1;
        const int kb = kt * 64;
        asm volatile("cp.async.wait_group 0;" ::: "memory");
        __syncthreads();
        if (kt + 1 < nkt) KV_LOAD(kb + 64, buf ^ 1);

        const uint32_t kB = sb + ATT_KOFF + (uint32_t)buf * ATT_BUFB;
        const uint32_t vB = sb + ATT_VOFF + (uint32_t)buf * ATT_BUFB;

        // S = (Q*scale*log2e) @ K^T  (log2-domain logits)
        float s[8][4];
#pragma unroll
        for (int j = 0; j < 8; j++)
#pragma unroll
            for (int e = 0; e < 4; e++) s[j][e] = 0.f;
#pragma unroll
        for (int kk4 = 0; kk4 < 4; kk4++) {
#pragma unroll
            for (int jp = 0; jp < 4; jp++) {
                uint32_t bk[4];
                ldsm4(bk, kB + swz((uint32_t)((jp * 16 + brow) * 128 +
                                              kk4 * 32 + bcolB)));
                mma_f16(s[2 * jp],     aq[kk4], &bk[0]);
                mma_f16(s[2 * jp + 1], aq[kk4], &bk[2]);
            }
        }

        // causal mask (only tiles crossing the diagonal); -30000 is f16-safe
        if (kb + 63 > row0) {
#pragma unroll
            for (int j = 0; j < 8; j++) {
                int c0 = kb + 8 * j + 2 * tig;
                if (c0 > row0)     s[j][0] = -30000.f;
                if (c0 + 1 > row0) s[j][1] = -30000.f;
                if (c0 > row1)     s[j][2] = -30000.f;
                if (c0 + 1 > row1) s[j][3] = -30000.f;
            }
        }

        // P = 2^S directly in f16 (static-max softmax)
        uint32_t pa[4][4];
#pragma unroll
        for (int kc = 0; kc < 4; kc++) {
            pa[kc][0] = ex2h2(s[2 * kc][0],     s[2 * kc][1]);
            pa[kc][1] = ex2h2(s[2 * kc][2],     s[2 * kc][3]);
            pa[kc][2] = ex2h2(s[2 * kc + 1][0], s[2 * kc + 1][1]);
            pa[kc][3] = ex2h2(s[2 * kc + 1][2], s[2 * kc + 1][3]);
        }

        // l += P @ ones  (row sums on tensor pipe, no shuffles)
#pragma unroll
        for (int kc = 0; kc < 4; kc++)
            mma_f16(lacc, pa[kc], onesb);

        // O += P @ V  (V fragments via ldmatrix.trans on [key][d] tile)
#pragma unroll
        for (int kc = 0; kc < 4; kc++)
#pragma unroll
            for (int jp = 0; jp < 4; jp++) {
                uint32_t bv[4];
                ldsm4t(bv, vB + swz((uint32_t)((kc * 16 + vrow) * 128 +
                                               jp * 32 + vcolB)));
                mma_f16(o[2 * jp],     pa[kc], &bv[0]);
                mma_f16(o[2 * jp + 1], pa[kc], &bv[2]);
            }
    }

    // normalize, store fp16 ctx  (lacc[0] = row0 sum, lacc[2] = row1 sum)
    const float inv0 = 1.f / lacc[0], inv1 = 1.f / lacc[2];
    const size_t r0g = rowb + qbase + w * 16 + gid;
#pragma unroll
    for (int j = 0; j < 8; j++) {
        int col = h * HDIM + 8 * j + 2 * tig;
        *(__half2*)(g_ctxh + r0g * DMODEL + col) =
            __floats2half2_rn(o[j][0] * inv0, o[j][1] * inv0);
        *(__half2*)(g_ctxh + (r0g + 8) * DMODEL + col) =
            __floats2half2_rn(o[j][2] * inv1, o[j][3] * inv1);
    }
}

// ---------------------------------------------------------------------------
extern "C" void kernel_launch(void* const* d_in, const int* in_sizes, int n_in,
                              void* d_out, int out_size) {
    const float* x     = (const float*)d_in[0];
    const float* w_qkv = (const float*)d_in[1];
    const float* w_out = (const float*)d_in[2];
    float* out = (float*)d_out;

    __half *xh, *wqh, *woh, *qkvh, *ctxh;
    cudaGetSymbolAddress((void**)&xh,   g_xh);
    cudaGetSymbolAddress((void**)&wqh,  g_wqkvh);
    cudaGetSymbolAddress((void**)&woh,  g_wouth);
    cudaGetSymbolAddress((void**)&qkvh, g_qkvh);
    cudaGetSymbolAddress((void**)&ctxh, g_ctxh);

    const int smemGemm = 2 * GBUF;  // 65536 B
    cudaFuncSetAttribute(hgemm<true>,
                         cudaFuncAttributeMaxDynamicSharedMemorySize, smemGemm);
    cudaFuncSetAttribute(hgemm<false>,
                         cudaFuncAttributeMaxDynamicSharedMemorySize, smemGemm);
    cudaFuncSetAttribute(attn_mma,
                         cudaFuncAttributeMaxDynamicSharedMemorySize, ATT_SMEM);

    to_half<<<256, 256>>>(x, xh, MROWS * DMODEL / 4);
    conv_wT<<<dim3(NQKV / 32, DMODEL / 32), 256>>>(w_qkv, wqh, DMODEL, NQKV);
    conv_wT<<<dim3(DMODEL / 32, DMODEL / 32), 256>>>(w_out, woh, DMODEL, DMODEL);

    // QKV projection (fp16 out): [8192,768] @ [768,2304]
    hgemm<true><<<dim3(NQKV / 128, MROWS / 128), 256, smemGemm>>>(
        xh, wqh, nullptr, qkvh, MROWS, NQKV, DMODEL);

    // causal attention -> ctx
    attn_mma<<<dim3(SLEN / 128, NHEADS, BATCH), 256, ATT_SMEM>>>();

    // output projection (fp32 out): [8192,768] @ [768,768]
    hgemm<false><<<dim3(DMODEL / 128, MROWS / 128), 256, smemGemm>>>(
        ctxh, woh, out, nullptr, MROWS, DMODEL, DMODEL);
}

// round 14
// speedup vs baseline: 1.0266x; 1.0206x over previous
#include <cuda_runtime.h>
#include <cuda_fp16.h>
#include <cstdint>
#include <cstddef>

#define SLEN   4096
#define BATCH  2
#define DMODEL 768
#define NHEADS 12
#define HDIM   64
#define MROWS  (BATCH * SLEN)   // 8192
#define NQKV   (3 * DMODEL)     // 2304

// ---------------- scratch (__device__ globals) -----------------------------
__device__ __half g_xh[(size_t)MROWS * DMODEL];
__device__ __half g_wqkvh[(size_t)DMODEL * NQKV];   // [N][K]
__device__ __half g_wouth[(size_t)DMODEL * DMODEL]; // [N][K]
__device__ __half g_qkvh[(size_t)MROWS * NQKV];     // fp16 Q|K|V
__device__ __half g_ctxh[(size_t)MROWS * DMODEL];

// ---------------- helpers --------------------------------------------------
__device__ __forceinline__ uint32_t s2u(const void* p) {
    return (uint32_t)__cvta_generic_to_shared(p);
}
__device__ __forceinline__ uint32_t swz(uint32_t b) {           // SW128
    return b ^ ((b >> 3) & 0x70);
}
__device__ __forceinline__ void ldsm4(uint32_t r[4], uint32_t addr) {
    asm volatile("ldmatrix.sync.aligned.m8n8.x4.shared.b16 {%0,%1,%2,%3}, [%4];"
                 : "=r"(r[0]), "=r"(r[1]), "=r"(r[2]), "=r"(r[3]) : "r"(addr));
}
__device__ __forceinline__ void ldsm4t(uint32_t r[4], uint32_t addr) {
    asm volatile("ldmatrix.sync.aligned.m8n8.x4.trans.shared.b16 {%0,%1,%2,%3}, [%4];"
                 : "=r"(r[0]), "=r"(r[1]), "=r"(r[2]), "=r"(r[3]) : "r"(addr));
}
__device__ __forceinline__ void cp16(uint32_t dst, const void* src) {
    asm volatile("cp.async.cg.shared.global [%0], [%1], 16;" :: "r"(dst), "l"(src));
}
__device__ __forceinline__ void mma_f16(float c[4], const uint32_t a[4],
                                        const uint32_t b[2]) {
    asm volatile(
        "mma.sync.aligned.m16n8k16.row.col.f32.f16.f16.f32 "
        "{%0,%1,%2,%3}, {%4,%5,%6,%7}, {%8,%9}, {%0,%1,%2,%3};\n"
        : "+f"(c[0]), "+f"(c[1]), "+f"(c[2]), "+f"(c[3])
        : "r"(a[0]), "r"(a[1]), "r"(a[2]), "r"(a[3]), "r"(b[0]), "r"(b[1]));
}
__device__ __forceinline__ unsigned pack2(float x, float y) {
    __half2 h = __floats2half2_rn(x, y);
    return *reinterpret_cast<unsigned*>(&h);
}
// 2^x on a packed half2 pair (inputs given as two floats)
__device__ __forceinline__ uint32_t ex2h2(float x, float y) {
    uint32_t h = pack2(x, y);
    uint32_t r;
    asm("ex2.approx.f16x2 %0, %1;" : "=r"(r) : "r"(h));
    return r;
}

// ---------------- converts -------------------------------------------------
__global__ void to_half(const float* __restrict__ src, __half* __restrict__ dst, int n4) {
    int i = blockIdx.x * blockDim.x + threadIdx.x;
    int stride = gridDim.x * blockDim.x;
    for (; i < n4; i += stride) {
        float4 v = reinterpret_cast<const float4*>(src)[i];
        reinterpret_cast<__half2*>(dst)[2 * i]     = __floats2half2_rn(v.x, v.y);
        reinterpret_cast<__half2*>(dst)[2 * i + 1] = __floats2half2_rn(v.z, v.w);
    }
}

// W[K][N] fp32 -> WT[N][K] fp16 (transpose + convert)
__global__ void conv_wT(const float* __restrict__ W, __half* __restrict__ WT,
                        int K, int N) {
    __shared__ float t[32][33];
    const int k0 = blockIdx.y * 32, n0 = blockIdx.x * 32;
    const int tx = threadIdx.x & 31, ty = threadIdx.x >> 5;
#pragma unroll
    for (int m = 0; m < 4; m++)
        t[ty + 8 * m][tx] = W[(size_t)(k0 + ty + 8 * m) * N + n0 + tx];
    __syncthreads();
#pragma unroll
    for (int m = 0; m < 4; m++)
        WT[(size_t)(n0 + ty + 8 * m) * K + k0 + tx] = __float2half_rn(t[tx][ty + 8 * m]);
}

// ---------------- 1-pass fp16 GEMM, BM=128 (QKV; proven) -------------------
#define GBUF 32768   // bytes per buffer (A 16K + B 16K)
__global__ __launch_bounds__(256, 2)
void hgemm128(const __half* __restrict__ A, const __half* __restrict__ Bt,
              __half* __restrict__ Ch, int M, int N, int K) {
    extern __shared__ __half sm[];
    const int tid = threadIdx.x, lane = tid & 31, w = tid >> 5;
    const int gid = lane >> 2, tig = lane & 3;
    const int wm = (w >> 2) * 64, wn = (w & 3) * 32;
    const int bm = blockIdx.y * 128, bn = blockIdx.x * 128;
    const uint32_t sb = s2u(sm);

    float acc[4][4][4];
#pragma unroll
    for (int i = 0; i < 4; i++)
#pragma unroll
        for (int j = 0; j < 4; j++)
#pragma unroll
            for (int e = 0; e < 4; e++) acc[i][j][e] = 0.f;

    const int nit = K >> 6;

#define G_LOAD(k0, buf)                                                         \
    {                                                                           \
        uint32_t bb = sb + (uint32_t)(buf) * GBUF;                              \
        _Pragma("unroll")                                                       \
        for (int p = 0; p < 4; p++) {                                           \
            int id = tid + p * 256;                                             \
            int row = id >> 3, chB = (id & 7) << 4;                             \
            uint32_t so = swz((uint32_t)(row * 128 + chB));                     \
            cp16(bb + so,                                                       \
                 (const char*)(A + (size_t)(bm + row) * K + (k0)) + chB);       \
            cp16(bb + 16384 + so,                                               \
                 (const char*)(Bt + (size_t)(bn + row) * K + (k0)) + chB);      \
        }                                                                       \
        asm volatile("cp.async.commit_group;" ::: "memory");                    \
    }

    G_LOAD(0, 0);

    const int arow  = lane & 15;
    const int acolB = ((lane >> 4) << 3) * 2;
    const int brow  = ((lane >> 4) << 3) + (lane & 7);
    const int bcolB = (((lane >> 3) & 1) << 3) * 2;

    for (int it = 0; it < nit; it++) {
        asm volatile("cp.async.wait_group 0;" ::: "memory");
        __syncthreads();
        if (it + 1 < nit) G_LOAD((it + 1) << 6, (it + 1) & 1);

        uint32_t aB = sb + (uint32_t)(it & 1) * GBUF;
        uint32_t bB = aB + 16384;
#pragma unroll
        for (int kk = 0; kk < 64; kk += 16) {
            uint32_t af[4][4];
#pragma unroll
            for (int i = 0; i < 4; i++)
                ldsm4(af[i], aB + swz((uint32_t)((wm + 16 * i + arow) * 128 +
                                                 kk * 2 + acolB)));
#pragma unroll
            for (int jp = 0; jp < 2; jp++) {
                uint32_t bh[4];
                ldsm4(bh, bB + swz((uint32_t)((wn + 16 * jp + brow) * 128 +
                                              kk * 2 + bcolB)));
#pragma unroll
                for (int i = 0; i < 4; i++) {
                    mma_f16(acc[i][2 * jp],     af[i], &bh[0]);
                    mma_f16(acc[i][2 * jp + 1], af[i], &bh[2]);
                }
            }
        }
        __syncthreads();
    }

#pragma unroll
    for (int i = 0; i < 4; i++)
#pragma unroll
        for (int j = 0; j < 4; j++) {
            int r0 = bm + wm + i * 16 + gid;
            int cc = bn + wn + j * 8 + 2 * tig;
            *(__half2*)(Ch + (size_t)r0 * N + cc) =
                __floats2half2_rn(acc[i][j][0], acc[i][j][1]);
            *(__half2*)(Ch + (size_t)(r0 + 8) * N + cc) =
                __floats2half2_rn(acc[i][j][2], acc[i][j][3]);
        }
}

// ---------------- BM=64 fp16 GEMM (out-proj; 2x blocks, better tail) -------
// Tile 64x128, BK=64, 8 warps (2m x 4n), warp tile 32x32. fp32 output.
#define GBUF64 24576   // A 8K + B 16K
__global__ __launch_bounds__(256, 2)
void hgemm64(const __half* __restrict__ A, const __half* __restrict__ Bt,
             float* __restrict__ Cf, int M, int N, int K) {
    extern __shared__ __half sm[];
    const int tid = threadIdx.x, lane = tid & 31, w = tid >> 5;
    const int gid = lane >> 2, tig = lane & 3;
    const int wm = (w >> 2) * 32, wn = (w & 3) * 32;
    const int bm = blockIdx.y * 64, bn = blockIdx.x * 128;
    const uint32_t sb = s2u(sm);

    float acc[2][4][4];
#pragma unroll
    for (int i = 0; i < 2; i++)
#pragma unroll
        for (int j = 0; j < 4; j++)
#pragma unroll
            for (int e = 0; e < 4; e++) acc[i][j][e] = 0.f;

    const int nit = K >> 6;

#define G_LOAD64(k0, buf)                                                       \
    {                                                                           \
        uint32_t bb = sb + (uint32_t)(buf) * GBUF64;                            \
        _Pragma("unroll")                                                       \
        for (int p = 0; p < 2; p++) {                                           \
            int id = tid + p * 256;                                             \
            int row = id >> 3, chB = (id & 7) << 4;                             \
            uint32_t so = swz((uint32_t)(row * 128 + chB));                     \
            cp16(bb + so,                                                       \
                 (const char*)(A + (size_t)(bm + row) * K + (k0)) + chB);       \
        }                                                                       \
        _Pragma("unroll")                                                       \
        for (int p = 0; p < 4; p++) {                                           \
            int id = tid + p * 256;                                             \
            int row = id >> 3, chB = (id & 7) << 4;                             \
            uint32_t so = swz((uint32_t)(row * 128 + chB));                     \
            cp16(bb + 8192 + so,                                                \
                 (const char*)(Bt + (size_t)(bn + row) * K + (k0)) + chB);      \
        }                                                                       \
        asm volatile("cp.async.commit_group;" ::: "memory");                    \
    }

    G_LOAD64(0, 0);

    const int arow  = lane & 15;
    const int acolB = ((lane >> 4) << 3) * 2;
    const int brow  = ((lane >> 4) << 3) + (lane & 7);
    const int bcolB = (((lane >> 3) & 1) << 3) * 2;

    for (int it = 0; it < nit; it++) {
        asm volatile("cp.async.wait_group 0;" ::: "memory");
        __syncthreads();
        if (it + 1 < nit) G_LOAD64((it + 1) << 6, (it + 1) & 1);

        uint32_t aB = sb + (uint32_t)(it & 1) * GBUF64;
        uint32_t bB = aB + 8192;
#pragma unroll
        for (int kk = 0; kk < 64; kk += 16) {
            uint32_t af[2][4];
#pragma unroll
            for (int i = 0; i < 2; i++)
                ldsm4(af[i], aB + swz((uint32_t)((wm + 16 * i + arow) * 128 +
                                                 kk * 2 + acolB)));
#pragma unroll
            for (int jp = 0; jp < 2; jp++) {
                uint32_t bh[4];
                ldsm4(bh, bB + swz((uint32_t)((wn + 16 * jp + brow) * 128 +
                                              kk * 2 + bcolB)));
#pragma unroll
                for (int i = 0; i < 2; i++) {
                    mma_f16(acc[i][2 * jp],     af[i], &bh[0]);
                    mma_f16(acc[i][2 * jp + 1], af[i], &bh[2]);
                }
            }
        }
        __syncthreads();
    }

#pragma unroll
    for (int i = 0; i < 2; i++)
#pragma unroll
        for (int j = 0; j < 4; j++) {
            int r0 = bm + wm + i * 16 + gid;
            int cc = bn + wn + j * 8 + 2 * tig;
            *(float2*)(Cf + (size_t)r0 * N + cc) =
                make_float2(acc[i][j][0], acc[i][j][1]);
            *(float2*)(Cf + (size_t)(r0 + 8) * N + cc) =
                make_float2(acc[i][j][2], acc[i][j][3]);
        }
}

// ---------------- fp16 flash attention, BQ=128, low-register S path --------
// Static-max softmax (p = 2^s), l via ones-MMA. S is processed in two
// j-halves with a 16-reg s buffer to keep total live regs < 128 (no spills).
// dyn smem bytes: Q[128][128B] @0; K[2][64][128B] @16384; V[2][64][128B] @32768
#define ATT_BUFB 8192
#define ATT_KOFF 16384
#define ATT_VOFF 32768
#define ATT_SMEM 49152
__global__ __launch_bounds__(256, 2)
void attn_mma() {
    extern __shared__ __half asm_[];
    const uint32_t sb = s2u(asm_);
    const int tid  = threadIdx.x;
    const int lane = tid & 31;
    const int w    = tid >> 5;
    const int gid  = lane >> 2;
    const int tig  = lane & 3;
    // Reverse order: heaviest q-tiles launch first.
    const int qt = gridDim.x - 1 - blockIdx.x;
    const int h = blockIdx.y, b = blockIdx.z;
    const int qbase = qt * 128;
    const size_t rowb = (size_t)b * SLEN;
    // Q pre-scale: (1/8) * log2(e) -> logits in log2 domain.
    const __half2 qscale = __floats2half2_rn(0.18033688f, 0.18033688f);

    // Load Q tile (128 rows x 64 halves = 128B rows), swizzled 8B stores
#pragma unroll
    for (int t = 0; t < 8; t++) {
        int c = tid + t * 256;
        int r = c >> 4, dc = (c & 15) << 2;
        uint2 v = *(const uint2*)(g_qkvh + (rowb + qbase + r) * NQKV + h * HDIM + dc);
        __half2 v0 = __hmul2(*reinterpret_cast<__half2*>(&v.x), qscale);
        __half2 v1 = __hmul2(*reinterpret_cast<__half2*>(&v.y), qscale);
        uint2 pkd = make_uint2(*(uint32_t*)&v0, *(uint32_t*)&v1);
        *(uint2*)((char*)asm_ + swz((uint32_t)(r * 128 + dc * 2))) = pkd;
    }

#define KV_LOAD(kb_, buf_)                                                         \
    {                                                                              \
        _Pragma("unroll")                                                          \
        for (int p = 0; p < 2; p++) {                                              \
            int id = tid + p * 256;                                                \
            int r = id >> 3, chB = (id & 7) << 4;                                  \
            uint32_t so = (uint32_t)(buf_) * ATT_BUFB +                            \
                          swz((uint32_t)(r * 128 + chB));                          \
            cp16(sb + ATT_KOFF + so,                                               \
                 (const char*)(g_qkvh + (rowb + (kb_) + r) * NQKV + DMODEL +       \
                               h * HDIM) + chB);                                   \
            cp16(sb + ATT_VOFF + so,                                               \
                 (const char*)(g_qkvh + (rowb + (kb_) + r) * NQKV + 2 * DMODEL +   \
                               h * HDIM) + chB);                                   \
        }                                                                          \
        asm volatile("cp.async.commit_group;" ::: "memory");                       \
    }

    float o[8][4];
#pragma unroll
    for (int j = 0; j < 8; j++)
#pragma unroll
        for (int e = 0; e < 4; e++) o[j][e] = 0.f;
    float lacc[4] = {0.f, 0.f, 0.f, 0.f};  // row sums via ones-MMA
    const uint32_t onesb[2] = {0x3C003C00u, 0x3C003C00u};

    const int arow  = lane & 15;
    const int acolB = ((lane >> 4) << 3) * 2;
    const int brow  = ((lane >> 4) << 3) + (lane & 7);
    const int bcolB = (((lane >> 3) & 1) << 3) * 2;
    const int vrow  = (lane & 7) + (((lane >> 3) & 1) << 3);
    const int vcolB = (lane >> 4) << 4;
    const int row0 = qbase + w * 16 + gid;
    const int row1 = row0 + 8;

    const int nkt = 2 * qt + 2;
    KV_LOAD(0, 0);

    // Hoist Q fragments into registers (Q smem stable across key loop)
    __syncthreads();
    uint32_t aq[4][4];
#pragma unroll
    for (int kk4 = 0; kk4 < 4; kk4++)
        ldsm4(aq[kk4], sb + swz((uint32_t)((w * 16 + arow) * 128 +
                                           kk4 * 32 + acolB)));

    for (int kt = 0; kt < nkt; kt++) {
        const int buf = kt & 1;
        const int kb = kt * 64;
        asm volatile("cp.async.wait_group 0;" ::: "memory");
        __syncthreads();
        if (kt + 1 < nkt) KV_LOAD(kb + 64, buf ^ 1);

        const uint32_t kB = sb + ATT_KOFF + (uint32_t)buf * ATT_BUFB;
        const uint32_t vB = sb + ATT_VOFF + (uint32_t)buf * ATT_BUFB;
        const bool diag = (kb + 63 > row0);

        // S and P in two j-halves: only 16 fp32 s regs live at a time.
        uint32_t pa[4][4];
#pragma unroll
        for (int hf = 0; hf < 2; hf++) {
            float s[4][4];
#pragma unroll
            for (int j = 0; j < 4; j++)
#pragma unroll
                for (int e = 0; e < 4; e++) s[j][e] = 0.f;
#pragma unroll
            for (int kk4 = 0; kk4 < 4; kk4++) {
#pragma unroll
                for (int jp2 = 0; jp2 < 2; jp2++) {
                    const int jp = 2 * hf + jp2;
                    uint32_t bk[4];
                    ldsm4(bk, kB + swz((uint32_t)((jp * 16 + brow) * 128 +
                                                  kk4 * 32 + bcolB)));
                    mma_f16(s[2 * jp2],     aq[kk4], &bk[0]);
                    mma_f16(s[2 * jp2 + 1], aq[kk4], &bk[2]);
                }
            }

            // causal mask (diagonal-crossing tiles only); -30000 is f16-safe
            if (diag) {
#pragma unroll
                for (int j = 0; j < 4; j++) {
                    int c0 = kb + 8 * (4 * hf + j) + 2 * tig;
                    if (c0 > row0)     s[j][0] = -30000.f;
                    if (c0 + 1 > row0) s[j][1] = -30000.f;
                    if (c0 > row1)     s[j][2] = -30000.f;
                    if (c0 + 1 > row1) s[j][3] = -30000.f;
                }
            }

            // P = 2^S directly in f16
#pragma unroll
            for (int c = 0; c < 2; c++) {
                const int kc = 2 * hf + c;
                pa[kc][0] = ex2h2(s[2 * c][0],     s[2 * c][1]);
                pa[kc][1] = ex2h2(s[2 * c][2],     s[2 * c][3]);
                pa[kc][2] = ex2h2(s[2 * c + 1][0], s[2 * c + 1][1]);
                pa[kc][3] = ex2h2(s[2 * c + 1][2], s[2 * c + 1][3]);
            }
        }

        // l += P @ ones  (row sums, no shuffles)
#pragma unroll
        for (int kc = 0; kc < 4; kc++)
            mma_f16(lacc, pa[kc], onesb);

        // O += P @ V  (V fragments via ldmatrix.trans on [key][d] tile)
#pragma unroll
        for (int kc = 0; kc < 4; kc++)
#pragma unroll
            for (int jp = 0; jp < 4; jp++) {
                uint32_t bv[4];
                ldsm4t(bv, vB + swz((uint32_t)((kc * 16 + vrow) * 128 +
                                               jp * 32 + vcolB)));
                mma_f16(o[2 * jp],     pa[kc], &bv[0]);
                mma_f16(o[2 * jp + 1], pa[kc], &bv[2]);
            }
    }

    // normalize, store fp16 ctx  (lacc[0] = row0 sum, lacc[2] = row1 sum)
    const float inv0 = 1.f / lacc[0], inv1 = 1.f / lacc[2];
    const size_t r0g = rowb + qbase + w * 16 + gid;
#pragma unroll
    for (int j = 0; j < 8; j++) {
        int col = h * HDIM + 8 * j + 2 * tig;
        *(__half2*)(g_ctxh + r0g * DMODEL + col) =
            __floats2half2_rn(o[j][0] * inv0, o[j][1] * inv0);
        *(__half2*)(g_ctxh + (r0g + 8) * DMODEL + col) =
            __floats2half2_rn(o[j][2] * inv1, o[j][3] * inv1);
    }
}

// ---------------------------------------------------------------------------
extern "C" void kernel_launch(void* const* d_in, const int* in_sizes, int n_in,
                              void* d_out, int out_size) {
    const float* x     = (const float*)d_in[0];
    const float* w_qkv = (const float*)d_in[1];
    const float* w_out = (const float*)d_in[2];
    float* out = (float*)d_out;

    __half *xh, *wqh, *woh, *qkvh, *ctxh;
    cudaGetSymbolAddress((void**)&xh,   g_xh);
    cudaGetSymbolAddress((void**)&wqh,  g_wqkvh);
    cudaGetSymbolAddress((void**)&woh,  g_wouth);
    cudaGetSymbolAddress((void**)&qkvh, g_qkvh);
    cudaGetSymbolAddress((void**)&ctxh, g_ctxh);

    const int smemG128 = 2 * GBUF;    // 65536 B
    const int smemG64  = 2 * GBUF64;  // 49152 B
    cudaFuncSetAttribute(hgemm128,
                         cudaFuncAttributeMaxDynamicSharedMemorySize, smemG128);
    cudaFuncSetAttribute(hgemm64,
                         cudaFuncAttributeMaxDynamicSharedMemorySize, smemG64);
    cudaFuncSetAttribute(attn_mma,
                         cudaFuncAttributeMaxDynamicSharedMemorySize, ATT_SMEM);

    to_half<<<256, 256>>>(x, xh, MROWS * DMODEL / 4);
    conv_wT<<<dim3(NQKV / 32, DMODEL / 32), 256>>>(w_qkv, wqh, DMODEL, NQKV);
    conv_wT<<<dim3(DMODEL / 32, DMODEL / 32), 256>>>(w_out, woh, DMODEL, DMODEL);

    // QKV projection (fp16 out): [8192,768] @ [768,2304]
    hgemm128<<<dim3(NQKV / 128, MROWS / 128), 256, smemG128>>>(
        xh, wqh, qkvh, MROWS, NQKV, DMODEL);

    // causal attention -> ctx
    attn_mma<<<dim3(SLEN / 128, NHEADS, BATCH), 256, ATT_SMEM>>>();

    // output projection (fp32 out): [8192,768] @ [768,768], BM=64 for tail
    hgemm64<<<dim3(DMODEL / 128, MROWS / 64), 256, smemG64>>>(
        ctxh, woh, out, MROWS, DMODEL, DMODEL);
}